// round 10
// baseline (speedup 1.0000x reference)
#include <cuda_runtime.h>
#include <math.h>

// Shapes (fixed by the problem)
#define T 2048
#define B 32
#define H 1024
#define KSPLIT 32          // k-tiles of 32 for the v GEMV
#define NCHUNK 16          // score-chunks per b (128 t each)

// Scratch (allocation-free rule: __device__ globals)
__device__ float g_vpart[KSPLIT][B][H];   // 4 MB split-k partials (L2-resident)
__device__ float g_v[B][H];               // 128 KB  v = hid @ W
__device__ float g_scores[B][T];          // 256 KB  pre-softmax scores
__device__ float g_pm[B][NCHUNK];         // per-chunk local max
__device__ float g_ps[B][NCHUNK];         // per-chunk local sum of exp
__device__ int   g_cnts[B];               // arrival counters (score chunks)

// ---------------------------------------------------------------------------
// K1: v_part[ks][b][h] = sum over k in [ks*32, ks*32+32) of hid[b,k]*W[k,h]
// Block = (128 h x 32 k); thread = one h, all 32 b's.
// KEY FIX vs R9: the 32 W loads are PREFETCHED into a fully-unrolled register
// array w[32] in a separate loop BEFORE any FMA — per-warp MLP = 32 cache
// lines instead of the load-use-chained MLP~1 ptxas produced before.
// W read exactly once chip-wide (4 MB, coalesced). Deterministic, no atomics.
// grid (hchunk=8, ksplit=32) = 256 blocks x 128 threads.
// ---------------------------------------------------------------------------
__global__ void __launch_bounds__(128) k_vpart(const float* __restrict__ hid,
                                               const float* __restrict__ W) {
    __shared__ float hid_s[B][32];
    const int tid   = threadIdx.x;                 // 0..127
    const int h     = blockIdx.x * 128 + tid;      // this thread's h
    const int kbase = blockIdx.y * 32;

    // load hid tile [32 b][32 k]: 1024 floats, 8 per thread
    for (int i = tid; i < B * 32; i += 128) {
        int bb = i >> 5, kk = i & 31;
        hid_s[bb][kk] = hid[bb * H + kbase + kk];
    }
    __syncthreads();

    // ---- front-batched W prefetch: 32 independent LDGs, no consumer between
    float w[32];
#pragma unroll
    for (int kk = 0; kk < 32; kk++) {
        w[kk] = __ldg(&W[(size_t)(kbase + kk) * H + h]);   // coalesced
    }

    float acc[B];
#pragma unroll
    for (int bb = 0; bb < B; bb++) acc[bb] = 0.f;

#pragma unroll
    for (int kk = 0; kk < 32; kk++) {
#pragma unroll
        for (int bb = 0; bb < B; bb++) acc[bb] += hid_s[bb][kk] * w[kk];
    }

#pragma unroll
    for (int bb = 0; bb < B; bb++) {
        g_vpart[blockIdx.y][bb][h] = acc[bb];       // coalesced across tid
    }
}

// ---------------------------------------------------------------------------
// K2: v[b][h] = sum over ksplit of v_part   (32768 elems; vpart sits in L2)
// ---------------------------------------------------------------------------
__global__ void __launch_bounds__(256) k_vreduce() {
    int idx = blockIdx.x * blockDim.x + threadIdx.x;
    const float* vp = &g_vpart[0][0][0];
    float* v = &g_v[0][0];
    if (idx < B * H) {
        float s = 0.f;
#pragma unroll
        for (int p = 0; p < KSPLIT; p++) s += vp[p * (B * H) + idx];
        v[idx] = s;
    }
}

// ---------------------------------------------------------------------------
// K3: scores + softmax, fused (byte-identical to R7/R8/R9).
// Block = one b x 128 t (8 warps x 16 t). grid 512 x 256.
// Stream body: v[b] in registers, all 128 enc loads per warp independent
// (__ldcs, max MLP), one pipelined butterfly strictly after all loads.
// Epilogue: warp (m,s) -> block partial -> global; 16th block per b merges
// and writes the final softmax outputs for its b (8 KB via L2).
// ---------------------------------------------------------------------------
__global__ void __launch_bounds__(256) k_scores(const float* __restrict__ enc,
                                                float* __restrict__ out) {
    __shared__ float sm_m[8], sm_s[8];
    __shared__ float sm_M, sm_inv;
    __shared__ int s_old;
    const int warp  = threadIdx.x >> 5;
    const int lane  = threadIdx.x & 31;
    const int b     = blockIdx.x >> 4;       // 0..31
    const int chunk = blockIdx.x & 15;       // 0..15
    const int tbase = chunk * 128 + warp * 16;

    // v[b] into registers: 8 float4 per lane (lane covers h = i*128 + lane*4)
    float4 vreg[8];
#pragma unroll
    for (int i = 0; i < 8; i++) {
        vreg[i] = *reinterpret_cast<const float4*>(&g_v[b][i * 128 + lane * 4]);
    }

    float acc[16];
#pragma unroll
    for (int tt = 0; tt < 16; tt++) {
        const int t = tbase + tt;
        const float4* e = reinterpret_cast<const float4*>(
            enc + ((size_t)t * B + b) * H) + lane;   // lane*4 floats in
        float4 a = make_float4(0.f, 0.f, 0.f, 0.f);
#pragma unroll
        for (int i = 0; i < 8; i++) {
            float4 ev = __ldcs(&e[i * 32]);          // h = i*128 + lane*4
            a.x += ev.x * vreg[i].x;
            a.y += ev.y * vreg[i].y;
            a.z += ev.z * vreg[i].z;
            a.w += ev.w * vreg[i].w;
        }
        acc[tt] = (a.x + a.y) + (a.z + a.w);
    }

    // Pipelined multi-value butterfly: 16 independent 5-stage chains.
#pragma unroll
    for (int off = 16; off > 0; off >>= 1) {
#pragma unroll
        for (int i = 0; i < 16; i++)
            acc[i] += __shfl_xor_sync(0xFFFFFFFFu, acc[i], off);
    }

    // per-warp softmax partial (computed after all loads retired)
    float mg = acc[0];
#pragma unroll
    for (int i = 1; i < 16; i++) mg = fmaxf(mg, acc[i]);
    float sg = 0.f;
#pragma unroll
    for (int i = 0; i < 16; i++) sg += __expf(acc[i] - mg);

    if (lane == 0) {
#pragma unroll
        for (int i = 0; i < 16; i++) g_scores[b][tbase + i] = acc[i];
        sm_m[warp] = mg;
        sm_s[warp] = sg;
    }
    __syncthreads();

    // merge 8 warp partials -> chunk partial; publish; take ticket
    if (threadIdx.x == 0) {
        float M = sm_m[0], S = sm_s[0];
#pragma unroll
        for (int i = 1; i < 8; i++) {
            float mi = sm_m[i];
            float nm = fmaxf(M, mi);
            S = S * __expf(M - nm) + sm_s[i] * __expf(mi - nm);
            M = nm;
        }
        g_pm[b][chunk] = M;
        g_ps[b][chunk] = S;
        __threadfence();                              // release
        s_old = atomicAdd(&g_cnts[b], 1);
    }
    __syncthreads();

    if (s_old == NCHUNK - 1) {                        // last chunk of this b
        __threadfence();                              // acquire
        if (threadIdx.x < 32) {
            float m = (lane < NCHUNK) ? g_pm[b][lane] : -INFINITY;
            float s = (lane < NCHUNK) ? g_ps[b][lane] : 0.f;
#pragma unroll
            for (int off = 8; off > 0; off >>= 1) {
                float mo = __shfl_xor_sync(0xFFFFFFFFu, m, off);
                float so = __shfl_xor_sync(0xFFFFFFFFu, s, off);
                float nm = fmaxf(m, mo);
                s = s * __expf(m - nm) + so * __expf(mo - nm);
                m = nm;
            }
            if (lane == 0) { sm_M = m; sm_inv = 1.f / s; }
        }
        __syncthreads();
        const float M = sm_M, inv = sm_inv;
#pragma unroll
        for (int j = 0; j < 2; j++) {
            const int t0 = j * 1024 + threadIdx.x * 4;
            float4 sc = *reinterpret_cast<const float4*>(&g_scores[b][t0]);
            float4 o;
            o.x = __expf(sc.x - M) * inv;
            o.y = __expf(sc.y - M) * inv;
            o.z = __expf(sc.z - M) * inv;
            o.w = __expf(sc.w - M) * inv;
            *reinterpret_cast<float4*>(&out[(size_t)b * T + t0]) = o;
        }
        if (threadIdx.x == 0) g_cnts[b] = 0;          // replay-safe reset
    }
}

// ---------------------------------------------------------------------------
// Inputs (metadata order): hidden [1,B,H], encoderOutput [T,B,H], W [H,H], b [H]
// Output: [B,1,T] float32.  Bias is constant in t -> cancels in softmax.
// ---------------------------------------------------------------------------
extern "C" void kernel_launch(void* const* d_in, const int* in_sizes, int n_in,
                              void* d_out, int out_size) {
    const float* hid = (const float*)d_in[0];
    const float* enc = (const float*)d_in[1];
    const float* W   = (const float*)d_in[2];
    (void)in_sizes; (void)n_in; (void)out_size;
    float* out = (float*)d_out;

    k_vpart<<<dim3(8, KSPLIT), 128>>>(hid, W);
    k_vreduce<<<(B * H + 255) / 256, 256>>>();
    k_scores<<<512, 256>>>(enc, out);
}

// round 11
// speedup vs baseline: 1.0360x; 1.0360x over previous
#include <cuda_runtime.h>
#include <math.h>

// Shapes (fixed by the problem)
#define T 2048
#define B 32
#define H 1024
#define KSPLIT 32          // k-tiles of 32 for the v GEMV
#define NCHUNK 16          // score-chunks per b (128 t each)

// Scratch (allocation-free rule: __device__ globals)
__device__ float g_vpart[KSPLIT][B][H];   // 4 MB split-k partials (L2-resident)
__device__ float g_v[B][H];               // 128 KB  v = hid @ W
__device__ float g_scores[B][T];          // 256 KB  pre-softmax scores
__device__ float g_pm[B][NCHUNK];         // per-chunk local max
__device__ float g_ps[B][NCHUNK];         // per-chunk local sum of exp
__device__ int   g_cnts[B];               // arrival counters (score chunks)

// ---------------------------------------------------------------------------
// K1: v_part[ks][b][h] = sum over k-tile of hid[b,k]*W[k,h]
// R10 post-mortem: kernel was issue/latency-bound (7 warps/SM x 2100 instr).
// Fix: (a) bsplit=4 -> 1024 blocks, ~28 warps/SM; (b) LDS.128 for hid ->
// per-thread 64 LDS + 256 FFMA instead of 1024+1024.
// grid (hchunk=8, ksplit=32, bsplit=4) = 1024 blocks x 128 threads.
// Thread: 1 h, 8 b, 32 k. w[32] front-batched. Deterministic, no atomics.
// ---------------------------------------------------------------------------
__global__ void __launch_bounds__(128) k_vpart(const float* __restrict__ hid,
                                               const float* __restrict__ W) {
    __shared__ float4 hid_s[8][8];                 // [bb][kk4]: 8 b x 32 k
    const int tid   = threadIdx.x;                 // 0..127
    const int h     = blockIdx.x * 128 + tid;      // this thread's h
    const int kbase = blockIdx.y * 32;
    const int bbase = blockIdx.z * 8;

    if (tid < 64) {
        int bb = tid >> 3, kk4 = tid & 7;
        hid_s[bb][kk4] = *reinterpret_cast<const float4*>(
            &hid[(bbase + bb) * H + kbase + kk4 * 4]);
    }
    __syncthreads();

    // front-batched W prefetch: 32 independent coalesced LDGs
    float w[32];
#pragma unroll
    for (int kk = 0; kk < 32; kk++) {
        w[kk] = __ldg(&W[(size_t)(kbase + kk) * H + h]);
    }

    float acc[8];
#pragma unroll
    for (int bb = 0; bb < 8; bb++) acc[bb] = 0.f;

#pragma unroll
    for (int bb = 0; bb < 8; bb++) {
#pragma unroll
        for (int kk4 = 0; kk4 < 8; kk4++) {
            float4 hv = hid_s[bb][kk4];            // one LDS.128, broadcast
            acc[bb] += hv.x * w[kk4 * 4 + 0];
            acc[bb] += hv.y * w[kk4 * 4 + 1];
            acc[bb] += hv.z * w[kk4 * 4 + 2];
            acc[bb] += hv.w * w[kk4 * 4 + 3];
        }
    }

#pragma unroll
    for (int bb = 0; bb < 8; bb++) {
        g_vpart[blockIdx.y][bbase + bb][h] = acc[bb];   // coalesced
    }
}

// ---------------------------------------------------------------------------
// K2: v[b][h] = sum over ksplit of v_part   (32768 elems; vpart sits in L2)
// ---------------------------------------------------------------------------
__global__ void __launch_bounds__(256) k_vreduce() {
    int idx = blockIdx.x * blockDim.x + threadIdx.x;
    const float* vp = &g_vpart[0][0][0];
    float* v = &g_v[0][0];
    if (idx < B * H) {
        float s = 0.f;
#pragma unroll
        for (int p = 0; p < KSPLIT; p++) s += vp[p * (B * H) + idx];
        v[idx] = s;
    }
}

// ---------------------------------------------------------------------------
// K3: scores + softmax, fused (byte-identical to R7..R10).
// Block = one b x 128 t (8 warps x 16 t). grid 512 x 256.
// Stream body: v[b] in registers, all 128 enc loads per warp independent
// (__ldcs, max MLP), one pipelined butterfly strictly after all loads.
// Epilogue: warp (m,s) -> block partial -> global; 16th block per b merges
// and writes the final softmax outputs for its b (8 KB via L2).
// ---------------------------------------------------------------------------
__global__ void __launch_bounds__(256) k_scores(const float* __restrict__ enc,
                                                float* __restrict__ out) {
    __shared__ float sm_m[8], sm_s[8];
    __shared__ float sm_M, sm_inv;
    __shared__ int s_old;
    const int warp  = threadIdx.x >> 5;
    const int lane  = threadIdx.x & 31;
    const int b     = blockIdx.x >> 4;       // 0..31
    const int chunk = blockIdx.x & 15;       // 0..15
    const int tbase = chunk * 128 + warp * 16;

    // v[b] into registers: 8 float4 per lane (lane covers h = i*128 + lane*4)
    float4 vreg[8];
#pragma unroll
    for (int i = 0; i < 8; i++) {
        vreg[i] = *reinterpret_cast<const float4*>(&g_v[b][i * 128 + lane * 4]);
    }

    float acc[16];
#pragma unroll
    for (int tt = 0; tt < 16; tt++) {
        const int t = tbase + tt;
        const float4* e = reinterpret_cast<const float4*>(
            enc + ((size_t)t * B + b) * H) + lane;   // lane*4 floats in
        float4 a = make_float4(0.f, 0.f, 0.f, 0.f);
#pragma unroll
        for (int i = 0; i < 8; i++) {
            float4 ev = __ldcs(&e[i * 32]);          // h = i*128 + lane*4
            a.x += ev.x * vreg[i].x;
            a.y += ev.y * vreg[i].y;
            a.z += ev.z * vreg[i].z;
            a.w += ev.w * vreg[i].w;
        }
        acc[tt] = (a.x + a.y) + (a.z + a.w);
    }

    // Pipelined multi-value butterfly: 16 independent 5-stage chains.
#pragma unroll
    for (int off = 16; off > 0; off >>= 1) {
#pragma unroll
        for (int i = 0; i < 16; i++)
            acc[i] += __shfl_xor_sync(0xFFFFFFFFu, acc[i], off);
    }

    // per-warp softmax partial (computed after all loads retired)
    float mg = acc[0];
#pragma unroll
    for (int i = 1; i < 16; i++) mg = fmaxf(mg, acc[i]);
    float sg = 0.f;
#pragma unroll
    for (int i = 0; i < 16; i++) sg += __expf(acc[i] - mg);

    if (lane == 0) {
#pragma unroll
        for (int i = 0; i < 16; i++) g_scores[b][tbase + i] = acc[i];
        sm_m[warp] = mg;
        sm_s[warp] = sg;
    }
    __syncthreads();

    // merge 8 warp partials -> chunk partial; publish; take ticket
    if (threadIdx.x == 0) {
        float M = sm_m[0], S = sm_s[0];
#pragma unroll
        for (int i = 1; i < 8; i++) {
            float mi = sm_m[i];
            float nm = fmaxf(M, mi);
            S = S * __expf(M - nm) + sm_s[i] * __expf(mi - nm);
            M = nm;
        }
        g_pm[b][chunk] = M;
        g_ps[b][chunk] = S;
        __threadfence();                              // release
        s_old = atomicAdd(&g_cnts[b], 1);
    }
    __syncthreads();

    if (s_old == NCHUNK - 1) {                        // last chunk of this b
        __threadfence();                              // acquire
        if (threadIdx.x < 32) {
            float m = (lane < NCHUNK) ? g_pm[b][lane] : -INFINITY;
            float s = (lane < NCHUNK) ? g_ps[b][lane] : 0.f;
#pragma unroll
            for (int off = 8; off > 0; off >>= 1) {
                float mo = __shfl_xor_sync(0xFFFFFFFFu, m, off);
                float so = __shfl_xor_sync(0xFFFFFFFFu, s, off);
                float nm = fmaxf(m, mo);
                s = s * __expf(m - nm) + so * __expf(mo - nm);
                m = nm;
            }
            if (lane == 0) { sm_M = m; sm_inv = 1.f / s; }
        }
        __syncthreads();
        const float M = sm_M, inv = sm_inv;
#pragma unroll
        for (int j = 0; j < 2; j++) {
            const int t0 = j * 1024 + threadIdx.x * 4;
            float4 sc = *reinterpret_cast<const float4*>(&g_scores[b][t0]);
            float4 o;
            o.x = __expf(sc.x - M) * inv;
            o.y = __expf(sc.y - M) * inv;
            o.z = __expf(sc.z - M) * inv;
            o.w = __expf(sc.w - M) * inv;
            *reinterpret_cast<float4*>(&out[(size_t)b * T + t0]) = o;
        }
        if (threadIdx.x == 0) g_cnts[b] = 0;          // replay-safe reset
    }
}

// ---------------------------------------------------------------------------
// Inputs (metadata order): hidden [1,B,H], encoderOutput [T,B,H], W [H,H], b [H]
// Output: [B,1,T] float32.  Bias is constant in t -> cancels in softmax.
// ---------------------------------------------------------------------------
extern "C" void kernel_launch(void* const* d_in, const int* in_sizes, int n_in,
                              void* d_out, int out_size) {
    const float* hid = (const float*)d_in[0];
    const float* enc = (const float*)d_in[1];
    const float* W   = (const float*)d_in[2];
    (void)in_sizes; (void)n_in; (void)out_size;
    float* out = (float*)d_out;

    k_vpart<<<dim3(8, KSPLIT, 4), 128>>>(hid, W);
    k_vreduce<<<(B * H + 255) / 256, 256>>>();
    k_scores<<<512, 256>>>(enc, out);
}